// round 3
// baseline (speedup 1.0000x reference)
#include <cuda_runtime.h>
#include <cstdint>

// Problem constants
#define B_  256
#define L_  500
#define E_  300
#define H_  10
#define K_  5

#define NT      512          // threads per block
#define NPAIR   25           // (K_*H_)/2 packed kh pairs
#define DOCS    2            // docs per CTA
#define DOCOFF  (L_ * E_ / 2)  // float2 offset between docs

// shared-memory layout (float offsets)
#define OFF_WP     0                         // 300*25 ull = 15000 floats (packed weights)
#define OFF_PROJ   15000                     // 50*500 = 25000 floats  proj[kh][l]
#define OFF_AE     40000                     // 150 floats aspEmbed (pad 160)
#define OFF_SC     40160                     // 2500 floats scores/attn
#define SMEM_FLOATS (OFF_SC + K_ * L_)       // 42660
#define SMEM_BYTES  (SMEM_FLOATS * 4)        // 170640 B

typedef unsigned long long ull;

__device__ __forceinline__ ull ffma2(ull a, ull b, ull c) {
    ull d;
    asm("fma.rn.f32x2 %0, %1, %2, %3;" : "=l"(d) : "l"(a), "l"(b), "l"(c));
    return d;
}
__device__ __forceinline__ ull pack2(float lo, float hi) {
    ull r;
    asm("mov.b64 %0, {%1, %2};" : "=l"(r) : "f"(lo), "f"(hi));
    return r;
}
__device__ __forceinline__ float2 unpack2(ull v) {
    float2 f;
    asm("mov.b64 {%0, %1}, %2;" : "=f"(f.x), "=f"(f.y) : "l"(v));
    return f;
}

__global__ __launch_bounds__(NT, 1)
void anr_arl_kernel(const float* __restrict__ review,
                    const float* __restrict__ aspProj,
                    const float* __restrict__ aspEmbed,
                    float* __restrict__ out)
{
    extern __shared__ float sm[];
    ull*   sWp     = reinterpret_cast<ull*>(sm + OFF_WP);    // [e*25 + p]
    float* sProj   = sm + OFF_PROJ;                           // [kh*500 + l] (reused per doc)
    float* sAE     = sm + OFF_AE;                             // [k*30 + h*3 + i]
    float* sScores = sm + OFF_SC;                             // [k*500 + l]

    const int tid = threadIdx.x;
    const int d0  = 2 * blockIdx.x;                           // docs d0, d0+1

    // ---- prologue: packed weights + aspEmbed into smem ----
    // Wp[e][p] = (aspProj[k,e,2p%H], aspProj[k,e,2p%H+1]); pairs never cross k (H even)
    for (int idx = tid; idx < E_ * NPAIR; idx += NT) {
        int e = idx / NPAIR, p = idx - e * NPAIR;
        int kh = 2 * p;
        int k = kh / H_, h = kh - k * H_;
        float2 w = *reinterpret_cast<const float2*>(aspProj + (k * E_ + e) * H_ + h);
        sWp[idx] = pack2(w.x, w.y);
    }
    for (int idx = tid; idx < K_ * 3 * H_; idx += NT) sAE[idx] = aspEmbed[idx];
    __syncthreads();

    // ---- GEMM: each thread computes proj[:, l] for row l in BOTH docs ----
    const bool active = (tid < L_);
    const int  lr     = active ? tid : 0;
    const float2* rp  = reinterpret_cast<const float2*>(
                            review + (size_t)d0 * (L_ * E_) + (size_t)lr * E_);
    const ull* sW = sWp;

    ull acc0[NPAIR], acc1[NPAIR];
#pragma unroll
    for (int p = 0; p < NPAIR; p++) { acc0[p] = 0ull; acc1[p] = 0ull; }

    float2 a0 = __ldg(rp);
    float2 a1 = __ldg(rp + DOCOFF);

#pragma unroll 1
    for (int eo = 0; eo < E_ / 2; eo++) {
        float2 c0 = a0, c1 = a1;
        if (eo < E_ / 2 - 1) {
            a0 = __ldg(rp + eo + 1);
            a1 = __ldg(rp + DOCOFF + eo + 1);
        }
        const ull* w = sW + (2 * eo) * NPAIR;

        ull p00 = pack2(c0.x, c0.x);
        ull p10 = pack2(c1.x, c1.x);
#pragma unroll
        for (int q = 0; q < NPAIR; q++) {
            ull wv = w[q];
            acc0[q] = ffma2(p00, wv, acc0[q]);
            acc1[q] = ffma2(p10, wv, acc1[q]);
        }
        ull p01 = pack2(c0.y, c0.y);
        ull p11 = pack2(c1.y, c1.y);
        const ull* w2 = w + NPAIR;
#pragma unroll
        for (int q = 0; q < NPAIR; q++) {
            ull wv = w2[q];
            acc0[q] = ffma2(p01, wv, acc0[q]);
            acc1[q] = ffma2(p11, wv, acc1[q]);
        }
    }

    // ---- epilogue, once per doc (reusing sProj/sScores) ----
    const int warp = tid >> 5, lane = tid & 31;

#pragma unroll 1
    for (int d = 0; d < DOCS; d++) {
        const int b = d0 + d;

        // write proj tile: proj[kh][l]
        if (active) {
#pragma unroll
            for (int p = 0; p < NPAIR; p++) {
                float2 v = unpack2(d == 0 ? acc0[p] : acc1[p]);
                sProj[(2 * p) * L_ + lr]     = v.x;
                sProj[(2 * p + 1) * L_ + lr] = v.y;
            }
        }
        __syncthreads();

        // window-3 attention scores: scores[k][l]
        for (int idx = tid; idx < K_ * L_; idx += NT) {
            int k = idx / L_, l = idx - k * L_;
            const float* aEk = sAE + k * 3 * H_;
            const float* pk  = sProj + k * H_ * L_;
            float s = 0.f;
#pragma unroll
            for (int i = 0; i < 3; i++) {
                int ll = l - 1 + i;
                if ((unsigned)ll < (unsigned)L_) {
#pragma unroll
                    for (int h = 0; h < H_; h++)
                        s += pk[h * L_ + ll] * aEk[h * 3 + i];
                }
            }
            sScores[idx] = s;
        }
        __syncthreads();

        // softmax over l per k (warp k), write attn out (B,K,L)
        if (warp < K_) {
            float* srow = sScores + warp * L_;
            float m = -3.402823466e38f;
            for (int l = lane; l < L_; l += 32) m = fmaxf(m, srow[l]);
#pragma unroll
            for (int o = 16; o > 0; o >>= 1) m = fmaxf(m, __shfl_xor_sync(0xffffffffu, m, o));
            float ssum = 0.f;
            for (int l = lane; l < L_; l += 32) {
                float ev = expf(srow[l] - m);
                srow[l] = ev;
                ssum += ev;
            }
#pragma unroll
            for (int o = 16; o > 0; o >>= 1) ssum += __shfl_xor_sync(0xffffffffu, ssum, o);
            float inv = 1.0f / ssum;
            float* oa = out + (size_t)b * (K_ * L_) + warp * L_;
            for (int l = lane; l < L_; l += 32) {
                float a = srow[l] * inv;
                srow[l] = a;
                oa[l] = a;
            }
        }
        __syncthreads();

        // pooled rep: rep[k][h] = sum_l proj[kh][l] * attn[k][l]  -> (B,K,H)
        float* orep = out + (size_t)B_ * K_ * L_ + (size_t)b * (K_ * H_);
        for (int kh = warp; kh < K_ * H_; kh += (NT / 32)) {
            int k = kh / H_;
            const float* pk = sProj + kh * L_;
            const float* ak = sScores + k * L_;
            float s = 0.f;
            for (int l = lane; l < L_; l += 32) s += pk[l] * ak[l];
#pragma unroll
            for (int o = 16; o > 0; o >>= 1) s += __shfl_xor_sync(0xffffffffu, s, o);
            if (lane == 0) orep[kh] = s;
        }
        __syncthreads();   // before next doc overwrites sProj
    }
}

extern "C" void kernel_launch(void* const* d_in, const int* in_sizes, int n_in,
                              void* d_out, int out_size)
{
    const float* review   = (const float*)d_in[0];
    const float* aspProj  = (const float*)d_in[1];
    const float* aspEmbed = (const float*)d_in[2];
    float* out = (float*)d_out;

    cudaFuncSetAttribute(anr_arl_kernel,
                         cudaFuncAttributeMaxDynamicSharedMemorySize, SMEM_BYTES);
    anr_arl_kernel<<<B_ / DOCS, NT, SMEM_BYTES>>>(review, aspProj, aspEmbed, out);
}

// round 4
// speedup vs baseline: 1.3990x; 1.3990x over previous
#include <cuda_runtime.h>
#include <cstdint>

// Problem constants
#define B_  256
#define L_  500
#define E_  300
#define H_  10
#define K_  5

#define NT      512          // threads per block (1 l-row per thread, 1 doc per CTA)
#define NPAIR   25           // (K_*H_)/2 packed kh pairs
#define WSTRIDE 26           // padded pairs per e (16B alignment for LDS.128)
#define EC      12           // e-columns per staging chunk
#define NCHUNK  25           // 300 / 12
#define RSROW   13           // EC + 1 pad; odd stride -> conflict-free strided LDS
#define RSBUF   (L_ * RSROW) // 6500 floats per staging buffer

// shared-memory layout (float offsets)
#define OFF_WP     0                          // 300*26 ull = 15600 floats (padded packed weights)
#define OFF_PROJ   15600                      // 50*500 = 25000 floats  proj[kh][l]
#define OFF_AE     40600                      // 150 floats aspEmbed (pad 160)
#define OFF_RS     40760                      // 2*6500 = 13000 floats staging (aliased as scores)
#define SMEM_FLOATS (OFF_RS + 2 * RSBUF)      // 53760
#define SMEM_BYTES  (SMEM_FLOATS * 4)         // 215040 B

typedef unsigned long long ull;

__device__ __forceinline__ ull ffma2(ull a, ull b, ull c) {
    ull d;
    asm("fma.rn.f32x2 %0, %1, %2, %3;" : "=l"(d) : "l"(a), "l"(b), "l"(c));
    return d;
}
__device__ __forceinline__ ull pack2(float lo, float hi) {
    ull r;
    asm("mov.b64 %0, {%1, %2};" : "=l"(r) : "f"(lo), "f"(hi));
    return r;
}
__device__ __forceinline__ float2 unpack2(ull v) {
    float2 f;
    asm("mov.b64 {%0, %1}, %2;" : "=f"(f.x), "=f"(f.y) : "l"(v));
    return f;
}

__global__ __launch_bounds__(NT, 1)
void anr_arl_kernel(const float* __restrict__ review,
                    const float* __restrict__ aspProj,
                    const float* __restrict__ aspEmbed,
                    float* __restrict__ out)
{
    extern __shared__ float sm[];
    ull*   sWp     = reinterpret_cast<ull*>(sm + OFF_WP);    // [e*26 + p], p<25 valid
    float* sProj   = sm + OFF_PROJ;                           // [kh*500 + l]
    float* sAE     = sm + OFF_AE;                             // [k*30 + h*3 + i]
    float* sRS     = sm + OFF_RS;                             // staging double buffer
    float* sScores = sRS;                                     // alias, used post-GEMM

    const int tid = threadIdx.x;
    const int b   = blockIdx.x;
    const float* revB = review + (size_t)b * (L_ * E_);
    const unsigned rs_u32 = (unsigned)__cvta_generic_to_shared(sRS);

    // ---- prologue: packed+padded weights and aspEmbed into smem ----
    // Wp[e][p] = (aspProj[k,e,2p%H], aspProj[k,e,2p%H+1]); pairs never cross k (H even)
    for (int idx = tid; idx < E_ * WSTRIDE; idx += NT) {
        int e = idx / WSTRIDE, p = idx - e * WSTRIDE;
        ull v = 0ull;
        if (p < NPAIR) {
            int kh = 2 * p;
            int k = kh / H_, h = kh - k * H_;
            float2 w = *reinterpret_cast<const float2*>(aspProj + (k * E_ + e) * H_ + h);
            v = pack2(w.x, w.y);
        }
        sWp[idx] = v;
    }
    for (int idx = tid; idx < K_ * 3 * H_; idx += NT) sAE[idx] = aspEmbed[idx];

    // ---- cp.async staging of review e-column chunks (coalesced-ish 4B ops) ----
    auto stage = [&](int c) {
        const float* src0 = revB + c * EC;
        const unsigned dbase = rs_u32 + (((unsigned)(c & 1) * RSBUF) << 2);
        for (int idx = tid; idx < L_ * EC; idx += NT) {
            int l = idx / EC, j = idx - l * EC;
            unsigned d = dbase + ((unsigned)(l * RSROW + j) << 2);
            const float* s = src0 + l * E_ + j;
            asm volatile("cp.async.ca.shared.global [%0], [%1], 4;" :: "r"(d), "l"(s) : "memory");
        }
        asm volatile("cp.async.commit_group;" ::: "memory");
    };

    const bool active = (tid < L_);
    const int  lr     = active ? tid : 0;      // inactive threads compute row 0, discard

    ull acc[NPAIR];
#pragma unroll
    for (int p = 0; p < NPAIR; p++) acc[p] = 0ull;

    stage(0);
    __syncthreads();   // also covers weight staging visibility

    const ulonglong2* W2 = reinterpret_cast<const ulonglong2*>(sWp);

    for (int c = 0; c < NCHUNK; c++) {
        if (c + 1 < NCHUNK) {
            stage(c + 1);
            asm volatile("cp.async.wait_group 1;" ::: "memory");
        } else {
            asm volatile("cp.async.wait_group 0;" ::: "memory");
        }
        __syncthreads();

        const float* rb = sRS + (c & 1) * RSBUF + lr * RSROW;
        const ulonglong2* Wc = W2 + (size_t)c * EC * (WSTRIDE / 2);

#pragma unroll 2
        for (int j = 0; j < EC; j++) {
            float a = rb[j];
            ull ap = pack2(a, a);
            const ulonglong2* w = Wc + j * (WSTRIDE / 2);
#pragma unroll
            for (int q = 0; q < WSTRIDE / 2; q++) {
                ulonglong2 wv = w[q];
                acc[2 * q] = ffma2(ap, wv.x, acc[2 * q]);
                if (2 * q + 1 < NPAIR)
                    acc[2 * q + 1] = ffma2(ap, wv.y, acc[2 * q + 1]);
            }
        }
        __syncthreads();   // before next iteration's stage overwrites this buffer
    }

    // ---- write proj tile to smem: proj[kh][l] ----
    if (active) {
#pragma unroll
        for (int p = 0; p < NPAIR; p++) {
            float2 v = unpack2(acc[p]);
            sProj[(2 * p) * L_ + lr]     = v.x;
            sProj[(2 * p + 1) * L_ + lr] = v.y;
        }
    }
    __syncthreads();

    // ---- window-3 attention scores: scores[k][l] ----
    for (int idx = tid; idx < K_ * L_; idx += NT) {
        int k = idx / L_, l = idx - k * L_;
        const float* aEk = sAE + k * 3 * H_;
        const float* pk  = sProj + k * H_ * L_;
        float s = 0.f;
#pragma unroll
        for (int i = 0; i < 3; i++) {
            int ll = l - 1 + i;
            if ((unsigned)ll < (unsigned)L_) {
#pragma unroll
                for (int h = 0; h < H_; h++)
                    s += pk[h * L_ + ll] * aEk[h * 3 + i];
            }
        }
        sScores[idx] = s;
    }
    __syncthreads();

    // ---- softmax over l per k (warp k), write attn out (B,K,L) ----
    const int warp = tid >> 5, lane = tid & 31;
    if (warp < K_) {
        float* srow = sScores + warp * L_;
        float m = -3.402823466e38f;
        for (int l = lane; l < L_; l += 32) m = fmaxf(m, srow[l]);
#pragma unroll
        for (int o = 16; o > 0; o >>= 1) m = fmaxf(m, __shfl_xor_sync(0xffffffffu, m, o));
        float ssum = 0.f;
        for (int l = lane; l < L_; l += 32) {
            float ev = expf(srow[l] - m);
            srow[l] = ev;
            ssum += ev;
        }
#pragma unroll
        for (int o = 16; o > 0; o >>= 1) ssum += __shfl_xor_sync(0xffffffffu, ssum, o);
        float inv = 1.0f / ssum;
        float* oa = out + (size_t)b * (K_ * L_) + warp * L_;
        for (int l = lane; l < L_; l += 32) {
            float a = srow[l] * inv;
            srow[l] = a;          // keep normalized attn in smem for pooling
            oa[l] = a;
        }
    }
    __syncthreads();

    // ---- pooled rep: rep[k][h] = sum_l proj[kh][l] * attn[k][l]  -> (B,K,H) ----
    float* orep = out + (size_t)B_ * K_ * L_ + (size_t)b * (K_ * H_);
    for (int kh = warp; kh < K_ * H_; kh += (NT / 32)) {
        int k = kh / H_;
        const float* pk = sProj + kh * L_;
        const float* ak = sScores + k * L_;
        float s = 0.f;
        for (int l = lane; l < L_; l += 32) s += pk[l] * ak[l];
#pragma unroll
        for (int o = 16; o > 0; o >>= 1) s += __shfl_xor_sync(0xffffffffu, s, o);
        if (lane == 0) orep[kh] = s;
    }
}

extern "C" void kernel_launch(void* const* d_in, const int* in_sizes, int n_in,
                              void* d_out, int out_size)
{
    const float* review   = (const float*)d_in[0];
    const float* aspProj  = (const float*)d_in[1];
    const float* aspEmbed = (const float*)d_in[2];
    float* out = (float*)d_out;

    cudaFuncSetAttribute(anr_arl_kernel,
                         cudaFuncAttributeMaxDynamicSharedMemorySize, SMEM_BYTES);
    anr_arl_kernel<<<B_, NT, SMEM_BYTES>>>(review, aspProj, aspEmbed, out);
}

// round 6
// speedup vs baseline: 4.4368x; 3.1715x over previous
#include <cuda_runtime.h>
#include <cuda_bf16.h>
#include <cstdint>

// Problem constants
#define B_  256
#define L_  500
#define E_  300
#define H_  10
#define K_  5

#define NT    512
#define NKS   19          // k-steps of 16 (covers 304, valid 300)
#define NNT   8           // n-tiles of 8 (64 cols, valid 50)

// shared memory layout (bytes)
#define SM_BHI   0
#define SM_BLO   (SM_BHI + NKS*512*4)        // 38912
#define SM_PROJ  (SM_BLO + NKS*512*4)        // 77824  (50*500*4 = 100000)
#define SM_SC    (SM_PROJ + 50*500*4)        // 177824 (2500*4 = 10000)
#define SM_AE    (SM_SC + K_*L_*4)           // 187824 (150*4 = 600, pad 640)
#define SMEM_BYTES (SM_AE + 640)             // 188464

__device__ __forceinline__ uint32_t cvt_bf2(float lo, float hi) {
    uint32_t d;
    asm("cvt.rn.bf16x2.f32 %0, %1, %2;" : "=r"(d) : "f"(hi), "f"(lo));
    return d;
}
// residual pair after removing bf16 hi parts
__device__ __forceinline__ uint32_t cvt_bf2_lo(float2 v, uint32_t hi) {
    float h0 = __uint_as_float(hi << 16);
    float h1 = __uint_as_float(hi & 0xFFFF0000u);
    return cvt_bf2(v.x - h0, v.y - h1);
}

__device__ __forceinline__ void mma_bf16(float* d, const uint32_t* a,
                                         uint32_t b0, uint32_t b1) {
    asm volatile(
        "mma.sync.aligned.m16n8k16.row.col.f32.bf16.bf16.f32 "
        "{%0,%1,%2,%3}, {%4,%5,%6,%7}, {%8,%9}, {%0,%1,%2,%3};"
        : "+f"(d[0]), "+f"(d[1]), "+f"(d[2]), "+f"(d[3])
        : "r"(a[0]), "r"(a[1]), "r"(a[2]), "r"(a[3]), "r"(b0), "r"(b1));
}

__global__ __launch_bounds__(NT, 1)
void anr_arl_kernel(const float* __restrict__ review,
                    const float* __restrict__ aspProj,
                    const float* __restrict__ aspEmbed,
                    float* __restrict__ out)
{
    extern __shared__ char smc[];
    uint32_t* sBhi   = reinterpret_cast<uint32_t*>(smc + SM_BHI);
    uint32_t* sBlo   = reinterpret_cast<uint32_t*>(smc + SM_BLO);
    float*    sProj  = reinterpret_cast<float*>(smc + SM_PROJ);   // [kh*500 + l]
    float*    sScores= reinterpret_cast<float*>(smc + SM_SC);     // [k*500 + l]
    float*    sAE    = reinterpret_cast<float*>(smc + SM_AE);

    const int tid  = threadIdx.x;
    const int wid  = tid >> 5, lane = tid & 31;
    const int b    = blockIdx.x;
    const float* revB = review + (size_t)b * (L_ * E_);

    // ---- stage B fragments: [ks][nt][r][lane] u32 = bf16 pair (k0, k0+1) ----
    // B[k][n] = aspProj[n/10, k, n%10]; hi = bf16(w), lo = bf16(w - hi)
    for (int idx = tid; idx < NKS * 512; idx += NT) {
        int lan = idx & 31;
        int r   = (idx >> 5) & 1;
        int nt  = (idx >> 6) & 7;
        int ks  = idx >> 9;
        int k0  = ks * 16 + ((lan & 3) << 1) + r * 8;
        int n   = nt * 8 + (lan >> 2);
        float w0 = 0.f, w1 = 0.f;
        if (n < 50) {
            int base = (n / H_) * (E_ * H_) + (n % H_);
            if (k0 < E_)     w0 = aspProj[base + k0 * H_];
            if (k0 + 1 < E_) w1 = aspProj[base + (k0 + 1) * H_];
        }
        uint32_t hi = cvt_bf2(w0, w1);
        float h0 = __uint_as_float(hi << 16);
        float h1 = __uint_as_float(hi & 0xFFFF0000u);
        uint32_t lo = cvt_bf2(w0 - h0, w1 - h1);
        sBhi[idx] = hi;
        sBlo[idx] = lo;
    }
    for (int i = tid; i < K_ * 3 * H_; i += NT) sAE[i] = aspEmbed[i];
    __syncthreads();

    // ---- GEMM mainloop: warp w owns rows [w*32, w*32+32), no syncs ----
    float acc[2][NNT][4];
#pragma unroll
    for (int t = 0; t < 2; t++)
#pragma unroll
        for (int nt = 0; nt < NNT; nt++)
#pragma unroll
            for (int c = 0; c < 4; c++) acc[t][nt][c] = 0.f;

    const int mrow0 = wid * 32;
    const int rquad = lane >> 2;          // 0..7
    const int cpair = (lane & 3) << 1;    // 0,2,4,6

#pragma unroll 1
    for (int ks = 0; ks < NKS; ks++) {
        const int kb = ks * 16;
        uint32_t ah[2][4], al[2][4];
#pragma unroll
        for (int t = 0; t < 2; t++) {
            int r0 = mrow0 + t * 16 + rquad;
            int r1 = r0 + 8;
            int rr0 = (r0 < L_) ? r0 : 0;
            int rr1 = (r1 < L_) ? r1 : 0;
            int c0 = kb + cpair;          // <= 294, always valid
            int c1 = c0 + 8;              // may exceed 299 on last step
            const float2 z = make_float2(0.f, 0.f);
            float2 v00 = *reinterpret_cast<const float2*>(revB + (size_t)rr0 * E_ + c0);
            float2 v10 = *reinterpret_cast<const float2*>(revB + (size_t)rr1 * E_ + c0);
            float2 v01 = (c1 < E_) ? *reinterpret_cast<const float2*>(revB + (size_t)rr0 * E_ + c1) : z;
            float2 v11 = (c1 < E_) ? *reinterpret_cast<const float2*>(revB + (size_t)rr1 * E_ + c1) : z;
            ah[t][0] = cvt_bf2(v00.x, v00.y);  al[t][0] = cvt_bf2_lo(v00, ah[t][0]);
            ah[t][1] = cvt_bf2(v10.x, v10.y);  al[t][1] = cvt_bf2_lo(v10, ah[t][1]);
            ah[t][2] = cvt_bf2(v01.x, v01.y);  al[t][2] = cvt_bf2_lo(v01, ah[t][2]);
            ah[t][3] = cvt_bf2(v11.x, v11.y);  al[t][3] = cvt_bf2_lo(v11, ah[t][3]);
        }
        const uint32_t* bh = sBhi + ks * 512;
        const uint32_t* bl = sBlo + ks * 512;
#pragma unroll
        for (int nt = 0; nt < NNT; nt++) {
            uint32_t b0h = bh[(nt * 2 + 0) * 32 + lane];
            uint32_t b1h = bh[(nt * 2 + 1) * 32 + lane];
            uint32_t b0l = bl[(nt * 2 + 0) * 32 + lane];
            uint32_t b1l = bl[(nt * 2 + 1) * 32 + lane];
#pragma unroll
            for (int t = 0; t < 2; t++) {
                mma_bf16(acc[t][nt], ah[t], b0h, b1h);   // hi*hi
                mma_bf16(acc[t][nt], ah[t], b0l, b1l);   // hi*lo
                mma_bf16(acc[t][nt], al[t], b0h, b1h);   // lo*hi
            }
        }
    }

    // ---- writeback acc -> sProj[kh][l] ----
#pragma unroll
    for (int t = 0; t < 2; t++) {
#pragma unroll
        for (int nt = 0; nt < NNT; nt++) {
#pragma unroll
            for (int c = 0; c < 4; c++) {
                int row = mrow0 + t * 16 + rquad + ((c >> 1) ? 8 : 0);
                int col = nt * 8 + cpair + (c & 1);
                if (row < L_ && col < 50)
                    sProj[col * L_ + row] = acc[t][nt][c];
            }
        }
    }
    __syncthreads();

    // ---- window-3 attention scores: scores[k][l] ----
    for (int idx = tid; idx < K_ * L_; idx += NT) {
        int k = idx / L_, l = idx - k * L_;
        const float* aEk = sAE + k * 3 * H_;
        const float* pk  = sProj + k * H_ * L_;
        float s = 0.f;
#pragma unroll
        for (int i = 0; i < 3; i++) {
            int ll = l - 1 + i;
            if ((unsigned)ll < (unsigned)L_) {
#pragma unroll
                for (int h = 0; h < H_; h++)
                    s += pk[h * L_ + ll] * aEk[h * 3 + i];
            }
        }
        sScores[idx] = s;
    }
    __syncthreads();

    // ---- softmax over l per k (warp k), write attn out (B,K,L) ----
    if (wid < K_) {
        float* srow = sScores + wid * L_;
        float m = -3.402823466e38f;
        for (int l = lane; l < L_; l += 32) m = fmaxf(m, srow[l]);
#pragma unroll
        for (int o = 16; o > 0; o >>= 1) m = fmaxf(m, __shfl_xor_sync(0xffffffffu, m, o));
        float ssum = 0.f;
        for (int l = lane; l < L_; l += 32) {
            float ev = expf(srow[l] - m);
            srow[l] = ev;
            ssum += ev;
        }
#pragma unroll
        for (int o = 16; o > 0; o >>= 1) ssum += __shfl_xor_sync(0xffffffffu, ssum, o);
        float inv = 1.0f / ssum;
        float* oa = out + (size_t)b * (K_ * L_) + wid * L_;
        for (int l = lane; l < L_; l += 32) {
            float a = srow[l] * inv;
            srow[l] = a;          // keep normalized attn for pooling
            oa[l] = a;
        }
    }
    __syncthreads();

    // ---- pooled rep: rep[k][h] = sum_l proj[kh][l] * attn[k][l]  -> (B,K,H) ----
    float* orep = out + (size_t)B_ * K_ * L_ + (size_t)b * (K_ * H_);
    for (int kh = wid; kh < K_ * H_; kh += (NT / 32)) {
        int k = kh / H_;
        const float* pk = sProj + kh * L_;
        const float* ak = sScores + k * L_;
        float s = 0.f;
        for (int l = lane; l < L_; l += 32) s += pk[l] * ak[l];
#pragma unroll
        for (int o = 16; o > 0; o >>= 1) s += __shfl_xor_sync(0xffffffffu, s, o);
        if (lane == 0) orep[kh] = s;
    }
}

extern "C" void kernel_launch(void* const* d_in, const int* in_sizes, int n_in,
                              void* d_out, int out_size)
{
    const float* review   = (const float*)d_in[0];
    const float* aspProj  = (const float*)d_in[1];
    const float* aspEmbed = (const float*)d_in[2];
    float* out = (float*)d_out;

    cudaFuncSetAttribute(anr_arl_kernel,
                         cudaFuncAttributeMaxDynamicSharedMemorySize, SMEM_BYTES);
    anr_arl_kernel<<<B_, NT, SMEM_BYTES>>>(review, aspProj, aspEmbed, out);
}